// round 4
// baseline (speedup 1.0000x reference)
#include <cuda_runtime.h>
#include <cstdint>

// VQ: for each token x (64-d), argmin_k ||x||^2 + ||c_k||^2 - 2 x.c_k over 1024 codes.
// Outputs (fp32, in order): quantized[N*64], loss[1], indices[N].
//
// Numerics vs JAX fp32 reference:
//  - dist = fmaf(-2, dot, sumx2 + sumc2)  == fp32((a+b) - 2m): identical rounding
//    sequence to the reference's elementwise (a + b) - 2*matmul.
//  - argmin uses monotone 64-bit keys (dist_bits<<32 | code_index): exact
//    first-index tie-break (jnp.argmin semantics), independent of reduction order.
//  - quantized output replicates straight-through rounding: x + (q - x).
//  - loss accumulated in Q30 fixed point (integer atomics) -> deterministic
//    across graph replays; loss = 1.25 * mean(best_dist).
//
// Compute path: packed fp32 FFMA2 (fma.rn.f32x2, sm_100+) -> 2 FMA per fma-pipe
// issue slot. 128-token x 128-code tiles, 8x8 register microtile per thread.

#define D        64
#define NCODES   1024
#define BT       128          // tokens per block
#define BC       128          // codes per chunk
#define NCHUNK   (NCODES / BC)
#define STRIDE   132          // padded smem row stride (floats): 132*4 % 16 == 0

// float-index offsets into dynamic smem
#define OFF_AS    0                          // As: [d][token]  64*132
#define OFF_BS    (D * STRIDE)               // Bs: [d][code]   64*132
#define OFF_SUMX2 (OFF_BS + D * STRIDE)      // 128
#define OFF_SC2   (OFF_SUMX2 + BT)           // 128
#define OFF_REDK  (OFF_SC2 + BC)             // u64[128][16] = 4096 float slots (8B aligned)
#define OFF_BIDX  (OFF_REDK + BT * 16 * 2)   // 128
#define OFF_PART  (OFF_BIDX + BT)            // u64[128] = 256 float slots (8B aligned)
#define SMEM_BYTES ((OFF_PART + 2 * BT) * 4) // 86528 B

typedef unsigned long long u64;

__device__ float g_ct[D * NCODES];            // codebook transposed: [d][k]
__device__ float g_sumc2[NCODES];
__device__ u64   g_loss_acc;

__device__ __forceinline__ void ffma2(u64& acc, u64 a, u64 b) {
    asm("fma.rn.f32x2 %0, %1, %2, %0;" : "+l"(acc) : "l"(a), "l"(b));
}
__device__ __forceinline__ u64 splat2(float v) {
    u64 r;
    asm("mov.b64 %0, {%1, %1};" : "=l"(r) : "f"(v));
    return r;
}
__device__ __forceinline__ void unpack2(u64 p, float& lo, float& hi) {
    asm("mov.b64 {%0, %1}, %2;" : "=f"(lo), "=f"(hi) : "l"(p));
}
__device__ __forceinline__ u64 make_key(float dist, int idx) {
    u64 k;
    asm("mov.b64 %0, {%1, %2};" : "=l"(k) : "r"(idx), "r"(__float_as_uint(dist)));
    return k;   // high word = dist bits (dist >= 0 -> monotone), low word = index
}

// ---------------------------------------------------------------------------
// Prep: transpose codebook, precompute ||c_k||^2, reset loss accumulator.
// ---------------------------------------------------------------------------
__global__ void prep_kernel(const float* __restrict__ codebook) {
    int k = threadIdx.x;
    if (k == 0) g_loss_acc = 0ull;
    float s = 0.f;
#pragma unroll 8
    for (int d = 0; d < D; d++) {
        float v = codebook[k * D + d];
        s = fmaf(v, v, s);
        g_ct[d * NCODES + k] = v;
    }
    g_sumc2[k] = s;
}

// ---------------------------------------------------------------------------
// Main kernel: 256 threads, 128 tokens/block, 8 tokens x 8 codes per thread.
// ---------------------------------------------------------------------------
__global__ __launch_bounds__(256, 2)
void vq_kernel(const float* __restrict__ x,
               const float* __restrict__ codebook,
               float* __restrict__ out_q,
               float* __restrict__ out_idx) {
    extern __shared__ float smem[];
    float* As    = smem + OFF_AS;
    float* Bs    = smem + OFF_BS;
    float* sumx2 = smem + OFF_SUMX2;
    float* sc2   = smem + OFF_SC2;
    u64*   redk  = (u64*)(smem + OFF_REDK);
    int*   bidx  = (int*)(smem + OFF_BIDX);
    u64*   part  = (u64*)(smem + OFF_PART);

    const int tid = threadIdx.x;
    const int t0  = blockIdx.x * BT;

    // Token tile, transposed into smem (global reads coalesced).
    for (int idx = tid; idx < BT * D; idx += 256) {
        int t = idx >> 6, d = idx & 63;
        As[d * STRIDE + t] = x[(size_t)(t0 + t) * D + d];
    }
    __syncthreads();

    // ||x||^2 per token
    if (tid < BT) {
        float s = 0.f;
#pragma unroll 8
        for (int d = 0; d < D; d++) {
            float v = As[d * STRIDE + tid];
            s = fmaf(v, v, s);
        }
        sumx2[tid] = s;
    }
    __syncthreads();

    const int ty = tid >> 4;   // token group (8 tokens)
    const int tx = tid & 15;   // code group  (8 codes)

    u64 bestk = 0xFFFFFFFFFFFFFFFFull;   // valid only for tid < BT (token tid)

    for (int ch = 0; ch < NCHUNK; ch++) {
        const int c0 = ch * BC;

        // Code chunk (pre-transposed -> coalesced, conflict-free)
        for (int idx = tid; idx < BC * D; idx += 256) {
            int d = idx >> 7, c = idx & 127;
            Bs[d * STRIDE + c] = g_ct[d * NCODES + c0 + c];
        }
        if (tid < BC) sc2[tid] = g_sumc2[c0 + tid];
        __syncthreads();

        // acc2[i][j2]: packed fp32 pair over codes (2*j2, 2*j2+1), token i
        u64 acc2[8][4];
#pragma unroll
        for (int i = 0; i < 8; i++)
#pragma unroll
            for (int j = 0; j < 4; j++) acc2[i][j] = 0ull;

#pragma unroll 2
        for (int d = 0; d < D; d++) {
            const float4 a0 = *(const float4*)&As[d * STRIDE + ty * 8];
            const float4 a1 = *(const float4*)&As[d * STRIDE + ty * 8 + 4];
            const ulonglong2 bA = *(const ulonglong2*)&Bs[d * STRIDE + tx * 8];
            const ulonglong2 bB = *(const ulonglong2*)&Bs[d * STRIDE + tx * 8 + 4];
            const u64 b[4] = {bA.x, bA.y, bB.x, bB.y};
            u64 as_[8];
            as_[0] = splat2(a0.x); as_[1] = splat2(a0.y);
            as_[2] = splat2(a0.z); as_[3] = splat2(a0.w);
            as_[4] = splat2(a1.x); as_[5] = splat2(a1.y);
            as_[6] = splat2(a1.z); as_[7] = splat2(a1.w);
#pragma unroll
            for (int i = 0; i < 8; i++)
#pragma unroll
                for (int j = 0; j < 4; j++)
                    ffma2(acc2[i][j], as_[i], b[j]);
        }

        // Per-thread argmin over its 8 codes, per token row, as 64-bit min-keys.
#pragma unroll
        for (int i = 0; i < 8; i++) {
            const float sxi = sumx2[ty * 8 + i];
            u64 bk = 0xFFFFFFFFFFFFFFFFull;
#pragma unroll
            for (int j = 0; j < 4; j++) {
                float mlo, mhi;
                unpack2(acc2[i][j], mlo, mhi);
                const int cidx = c0 + tx * 8 + 2 * j;
                // dist = fp32((sumx2 + sumc2) - 2*dot): one add, one fused fma
                float dlo = fmaf(-2.f, mlo, sxi + sc2[tx * 8 + 2 * j]);
                float dhi = fmaf(-2.f, mhi, sxi + sc2[tx * 8 + 2 * j + 1]);
                u64 klo = make_key(dlo, cidx);
                u64 khi = make_key(dhi, cidx + 1);
                if (klo < bk) bk = klo;
                if (khi < bk) bk = khi;
            }
            redk[(ty * 8 + i) * 16 + tx] = bk;
        }
        __syncthreads();

        // Cross-thread reduce: min over keys (order-independent, exact tie-break)
        if (tid < BT) {
#pragma unroll
            for (int s = 0; s < 16; s++) {
                u64 k = redk[tid * 16 + s];
                if (k < bestk) bestk = k;
            }
        }
        __syncthreads();
    }

    // Epilogue
    if (tid < BT) {
        const int   besti = (int)(bestk & 0xFFFFFFFFull);
        const float bestd = __uint_as_float((unsigned)(bestk >> 32));
        bidx[tid] = besti;
        out_idx[t0 + tid] = (float)besti;
        part[tid] = (u64)llrintf(bestd * 1073741824.f);   // Q30 fixed point
    }
    __syncthreads();
    if (tid == 0) {
        u64 s = 0;
        for (int i = 0; i < BT; i++) s += part[i];
        atomicAdd(&g_loss_acc, s);
    }

    // Quantized output, coalesced; straight-through rounding x + (q - x)
    for (int idx = tid; idx < BT * D; idx += 256) {
        int t = idx >> 6, d = idx & 63;
        float q  = __ldg(&codebook[(size_t)bidx[t] * D + d]);
        float xv = x[(size_t)(t0 + t) * D + d];
        out_q[(size_t)(t0 + t) * D + d] = xv + (q - xv);
    }
}

// ---------------------------------------------------------------------------
// Finalize: loss = m + 0.25*m, m = mean(best_dist) over N*D elements
// ---------------------------------------------------------------------------
__global__ void finalize_kernel(float* __restrict__ out_loss, double inv_count) {
    double s = (double)g_loss_acc * (1.0 / 1073741824.0);
    float  m = (float)(s * inv_count);
    out_loss[0] = m + 0.25f * m;
}

extern "C" void kernel_launch(void* const* d_in, const int* in_sizes, int n_in,
                              void* d_out, int out_size) {
    const float* x  = (const float*)d_in[0];
    const float* cb = (const float*)d_in[1];
    float* out = (float*)d_out;

    const int n = in_sizes[0] / D;          // 262144 tokens
    float* out_q    = out;
    float* out_loss = out + (size_t)n * D;
    float* out_idx  = out_loss + 1;

    cudaFuncSetAttribute(vq_kernel, cudaFuncAttributeMaxDynamicSharedMemorySize,
                         SMEM_BYTES);

    prep_kernel<<<1, NCODES>>>(cb);
    vq_kernel<<<n / BT, 256, SMEM_BYTES>>>(x, cb, out_q, out_idx);
    finalize_kernel<<<1, 1>>>(out_loss, 1.0 / ((double)n * D));
}

// round 6
// speedup vs baseline: 1.0248x; 1.0248x over previous
#include <cuda_runtime.h>
#include <cuda_bf16.h>
#include <cstdint>

// VQ-VAE quantizer: warp-level bf16 MMA (mma.sync, sm_100-safe) candidate search
// + bit-exact fp32 refinement (identical arithmetic to the round-4 rel_err=0.0 path).
//
//  Stage A: acc[t,k] = dot(bf16(x_t), bf16(c_k)) in fp32 via mma.sync.m16n8k16.
//    dist ~= -2*acc (we fold ||c||^2 <= 6.1e-5 and all bf16 truncation error into
//    the margin). Candidates: codes with acc >= max_acc - EPS_ACC.
//  Stage B: candidates re-scored exactly (sequential-d fmaf dot; dist =
//    fmaf(-2,dot,sx+sc2); first-index tie-break via monotone u64 keys).
//  Safety: per-token overflow flag -> cooperative exact rescan of all 1024 codes.

typedef unsigned long long u64;
typedef unsigned int u32;

#define D        64
#define NCODES   1024
#define BT       128          // tokens per block
#define CHUNK    128          // codes per smem chunk
#define NCHUNK   8
#define NBLOCKS  2048
#define EPS_ACC  4e-4f        // acc-units margin (dist margin = 8e-4)
#define CAP      6
#define RSTRIDE  144          // bytes per padded row (72 bf16): conflict-free ldmatrix

// ---- smem byte offsets ----
#define SB_XH    0            // x_hi bf16 tile [128][72h]        18432
#define SB_B0    18432        // code chunk buf0 [128][72h]       18432
#define SB_B1    36864        // code chunk buf1                  18432
#define SB_SC2   55296        // f32[1024]                         4096
#define SB_CAND  59392        // u64[128][4][CAP]                 24576
#define SB_CNT   83968        // i32[128][4]                       2048
#define SB_VB    86016        // f32[128][4]                       2048
#define SB_BIDX  88064        // i32[128]                           512
#define SB_PART  88576        // u64[128]                          1024
#define SB_FLAG  89600        // i32[128]                           512
#define SB_SCR   90112        // u64 key scratch + f32 sx            16
#define SMEM_TOTAL 90144

__device__ __align__(16) unsigned char g_ctile[NCODES * RSTRIDE];  // bf16 codes, padded rows
__device__ float g_sumc2[NCODES];
__device__ u64   g_block_loss[NBLOCKS];

// ---- ptx helpers ----
__device__ __forceinline__ u32 smem_u32(const void* p) {
    u32 a; asm("{ .reg .u64 t; cvta.to.shared.u64 t, %1; cvt.u32.u64 %0, t; }" : "=r"(a) : "l"(p));
    return a;
}
__device__ __forceinline__ void cp16(u32 saddr, const void* g) {
    asm volatile("{ .reg .u64 gp; cvta.to.global.u64 gp, %1;"
                 " cp.async.cg.shared.global [%0], [gp], 16; }"
                 :: "r"(saddr), "l"(g) : "memory");
}
#define CP_COMMIT() asm volatile("cp.async.commit_group;" ::: "memory")
#define CP_WAIT1()  asm volatile("cp.async.wait_group 1;" ::: "memory")
#define CP_WAIT0()  asm volatile("cp.async.wait_group 0;" ::: "memory")

__device__ __forceinline__ void ldmx4(u32* r, u32 a) {
    asm volatile("ldmatrix.sync.aligned.m8n8.x4.shared.b16 {%0,%1,%2,%3}, [%4];"
                 : "=r"(r[0]), "=r"(r[1]), "=r"(r[2]), "=r"(r[3]) : "r"(a));
}
__device__ __forceinline__ void ldmx2(u32& b0, u32& b1, u32 a) {
    asm volatile("ldmatrix.sync.aligned.m8n8.x2.shared.b16 {%0,%1}, [%2];"
                 : "=r"(b0), "=r"(b1) : "r"(a));
}
__device__ __forceinline__ void mma16816(float& c0, float& c1, float& c2, float& c3,
                                         const u32* a, u32 b0, u32 b1) {
    asm volatile("mma.sync.aligned.m16n8k16.row.col.f32.bf16.bf16.f32 "
                 "{%0,%1,%2,%3}, {%4,%5,%6,%7}, {%8,%9}, {%0,%1,%2,%3};"
                 : "+f"(c0), "+f"(c1), "+f"(c2), "+f"(c3)
                 : "r"(a[0]), "r"(a[1]), "r"(a[2]), "r"(a[3]), "r"(b0), "r"(b1));
}

// Exact re-score: arithmetic identical to the round-4 (rel_err = 0.0) kernel.
__device__ __forceinline__ u64 exact_key(const float* __restrict__ xr,
                                         const float* __restrict__ cb,
                                         const float* __restrict__ sc2s,
                                         float sx, int ci) {
    const float* cr = cb + (size_t)ci * D;
    float dot = 0.f;
#pragma unroll 16
    for (int d = 0; d < D; d++) dot = fmaf(xr[d], cr[d], dot);
    float dist = fmaf(-2.f, dot, sx + sc2s[ci]);
    return ((u64)__float_as_uint(dist) << 32) | (u32)ci;
}

__device__ __forceinline__ float exact_sx(const float* __restrict__ xr) {
    float sx = 0.f;
#pragma unroll 16
    for (int d = 0; d < D; d++) sx = fmaf(xr[d], xr[d], sx);
    return sx;
}

// Candidate insert: threshold vs running subset max; compaction on overflow.
__device__ __forceinline__ void insert(float v, int idx, float& vb, int& cnt, int& flg,
                                       u64* list, int* flagarr, int token) {
    if (v > vb) vb = v;
    if (v >= vb - EPS_ACC && !flg) {
        u64 e = ((u64)__float_as_uint(v) << 32) | (u32)idx;
        if (cnt < CAP) {
            list[cnt++] = e;
        } else {
            u64 keep[CAP];
            int m = 0;
            float th = vb - EPS_ACC;
#pragma unroll
            for (int s = 0; s < CAP; s++) {
                u64 ee = list[s];
                if (__uint_as_float((u32)(ee >> 32)) >= th) keep[m++] = ee;
            }
            if (m < CAP) {
                keep[m++] = e;
#pragma unroll
                for (int s = 0; s < CAP; s++) if (s < m) list[s] = keep[s];
                cnt = m;
            } else {
                flg = 1;
                flagarr[token] = 1;   // ultra-rare: full exact rescan
            }
        }
    }
}

// ---------------------------------------------------------------------------
// Prep: bf16 codebook rows (padded to 144B) + exact ||c||^2 (sequential fma).
// ---------------------------------------------------------------------------
__global__ void prep_kernel(const float* __restrict__ cb) {
    const int c = blockIdx.x * 128 + threadIdx.x;
    float s = 0.f;
    unsigned char* row = g_ctile + (size_t)c * RSTRIDE;
#pragma unroll 8
    for (int d = 0; d < D; d += 2) {
        float v0 = cb[(size_t)c * D + d];
        float v1 = cb[(size_t)c * D + d + 1];
        s = fmaf(v0, v0, s);
        s = fmaf(v1, v1, s);
        *(ushort2*)(row + 2 * d) = make_ushort2(
            __bfloat16_as_ushort(__float2bfloat16_rn(v0)),
            __bfloat16_as_ushort(__float2bfloat16_rn(v1)));
    }
    *(uint4*)(row + 128) = make_uint4(0, 0, 0, 0);   // pad halves 64..71
    g_sumc2[c] = s;
}

// ---------------------------------------------------------------------------
// Main kernel: 256 threads (8 warps), 128 tokens/block; warp w owns tokens
// [w*16, w*16+16). Codes streamed in 128-code chunks, double-buffered.
// ---------------------------------------------------------------------------
__global__ __launch_bounds__(256, 2)
void vq_kernel(const float* __restrict__ x,
               const float* __restrict__ cb,
               float* __restrict__ out_q,
               float* __restrict__ out_idx) {
    extern __shared__ char smem[];
    const u32 sb  = smem_u32(smem);
    const int tid  = threadIdx.x;
    const int lane = tid & 31;
    const int w    = tid >> 5;
    const int t0   = blockIdx.x * BT;

    float* sc2s = (float*)(smem + SB_SC2);
    u64*   cand = (u64*)(smem + SB_CAND);
    int*   cnts = (int*)(smem + SB_CNT);
    float* vbs  = (float*)(smem + SB_VB);
    int*   bidx = (int*)(smem + SB_BIDX);
    u64*   part = (u64*)(smem + SB_PART);
    int*   flag = (int*)(smem + SB_FLAG);

    // Prefetch code chunk 0
    for (u32 off = tid * 16; off < CHUNK * RSTRIDE; off += 256 * 16)
        cp16(sb + SB_B0 + off, g_ctile + off);
    CP_COMMIT();

    // Build x_hi bf16 tile (coalesced gmem reads)
    for (int idx = tid; idx < BT * 32; idx += 256) {
        int t = idx >> 5, p = idx & 31;
        float2 v = *(const float2*)&x[(size_t)(t0 + t) * D + 2 * p];
        *(ushort2*)(smem + SB_XH + t * RSTRIDE + 4 * p) = make_ushort2(
            __bfloat16_as_ushort(__float2bfloat16_rn(v.x)),
            __bfloat16_as_ushort(__float2bfloat16_rn(v.y)));
    }
    for (int i = tid; i < NCODES; i += 256) sc2s[i] = g_sumc2[i];
    if (tid < BT) flag[tid] = 0;
    __syncthreads();

    // A fragments for this warp's 16 tokens (held in registers, K=64)
    u32 a[4][4];
    {
        u32 abase = sb + SB_XH + (w * 16 + (lane & 15)) * RSTRIDE + ((lane >> 4) & 1) * 16;
#pragma unroll
        for (int k = 0; k < 4; k++) ldmx4(a[k], abase + k * 32);
    }

    const int sub  = lane & 3;                 // n-column subgroup
    const int row0 = w * 16 + (lane >> 2);     // token index (within block)
    const int row1 = row0 + 8;
    u64* list0 = cand + (row0 * 4 + sub) * CAP;
    u64* list1 = cand + (row1 * 4 + sub) * CAP;
    const u32 lmoff = (lane & 7) * RSTRIDE + ((lane >> 3) & 1) * 16;

    float vb0 = -1e30f, vb1 = -1e30f;
    int   cnt0 = 0, cnt1 = 0, flg0 = 0, flg1 = 0;

    for (int ch = 0; ch < NCHUNK; ch++) {
        if (ch + 1 < NCHUNK) {   // prefetch next chunk into other buffer
            u32 dst = sb + (((ch + 1) & 1) ? SB_B1 : SB_B0);
            const unsigned char* src = g_ctile + (size_t)(ch + 1) * CHUNK * RSTRIDE;
            for (u32 off = tid * 16; off < CHUNK * RSTRIDE; off += 256 * 16)
                cp16(dst + off, src + off);
            CP_COMMIT();
            CP_WAIT1();          // current chunk resident
        } else {
            CP_WAIT0();
        }
        __syncthreads();

        const u32 bbase = sb + ((ch & 1) ? SB_B1 : SB_B0) + lmoff;
        const int cbase = ch * CHUNK;

#pragma unroll 4
        for (int tile = 0; tile < 16; tile++) {
            float c0 = 0.f, c1 = 0.f, c2 = 0.f, c3 = 0.f;
            const u32 ta = bbase + tile * (8 * RSTRIDE);
#pragma unroll
            for (int k = 0; k < 4; k++) {
                u32 b0, b1;
                ldmx2(b0, b1, ta + k * 32);
                mma16816(c0, c1, c2, c3, a[k], b0, b1);
            }
            const int ci = cbase + tile * 8 + 2 * sub;
            insert(c0, ci,     vb0, cnt0, flg0, list0, flag, row0);
            insert(c1, ci + 1, vb0, cnt0, flg0, list0, flag, row0);
            insert(c2, ci,     vb1, cnt1, flg1, list1, flag, row1);
            insert(c3, ci + 1, vb1, cnt1, flg1, list1, flag, row1);
        }
        __syncthreads();   // all warps done with this buffer before it is refilled
    }

    vbs[row0 * 4 + sub] = vb0;  cnts[row0 * 4 + sub] = cnt0;
    vbs[row1 * 4 + sub] = vb1;  cnts[row1 * 4 + sub] = cnt1;
    __syncthreads();

    // ---- Exact refinement (token = tid for tid < 128) ----
    if (tid < BT && !flag[tid]) {
        const int t = tid;
        float m0 = vbs[t * 4 + 0], m1 = vbs[t * 4 + 1];
        float m2 = vbs[t * 4 + 2], m3 = vbs[t * 4 + 3];
        float thr = fmaxf(fmaxf(m0, m1), fmaxf(m2, m3)) - EPS_ACC;

        const float* xr = x + (size_t)(t0 + t) * D;
        const float sx  = exact_sx(xr);
        u64 bestk = 0xFFFFFFFFFFFFFFFFull;
        for (int l4 = 0; l4 < 4; l4++) {
            const int n = cnts[t * 4 + l4];
            const u64* ls = cand + (t * 4 + l4) * CAP;
            for (int e = 0; e < n; e++) {
                u64 ee = ls[e];
                if (__uint_as_float((u32)(ee >> 32)) < thr) continue;
                u64 key = exact_key(xr, cb, sc2s, sx, (int)(ee & 0xFFFFFFFFull));
                if (key < bestk) bestk = key;
            }
        }
        const int   besti = (int)(bestk & 0xFFFFFFFFull);
        const float bestd = __uint_as_float((u32)(bestk >> 32));
        bidx[t] = besti;
        out_idx[t0 + t] = (float)besti;
        part[t] = (u64)llrintf(bestd * 1073741824.f);    // Q30 fixed point
    }
    __syncthreads();

    // ---- Cooperative full rescan for flagged tokens (probability ~0) ----
    for (int t = 0; t < BT; t++) {
        if (!flag[t]) continue;                    // uniform across block
        if (tid == 0) {
            *(u64*)(smem + SB_SCR) = 0xFFFFFFFFFFFFFFFFull;
            *(float*)(smem + SB_SCR + 8) = exact_sx(x + (size_t)(t0 + t) * D);
        }
        __syncthreads();
        const float sxt = *(float*)(smem + SB_SCR + 8);
        const float* xr = x + (size_t)(t0 + t) * D;
        for (int c = tid; c < NCODES; c += 256) {
            u64 key = exact_key(xr, cb, sc2s, sxt, c);
            atomicMin((u64*)(smem + SB_SCR), key);
        }
        __syncthreads();
        if (tid == 0) {
            u64 bk = *(u64*)(smem + SB_SCR);
            const int   besti = (int)(bk & 0xFFFFFFFFull);
            const float bestd = __uint_as_float((u32)(bk >> 32));
            bidx[t] = besti;
            out_idx[t0 + t] = (float)besti;
            part[t] = (u64)llrintf(bestd * 1073741824.f);
        }
        __syncthreads();
    }

    if (tid == 0) {
        u64 s = 0;
        for (int k = 0; k < BT; k++) s += part[k];
        g_block_loss[blockIdx.x] = s;              // fresh write: deterministic
    }

    // Quantized output, coalesced; straight-through rounding x + (q - x)
    for (int idx = tid; idx < BT * D; idx += 256) {
        int t = idx >> 6, d = idx & 63;
        float q  = __ldg(&cb[(size_t)bidx[t] * D + d]);
        float xv = x[(size_t)(t0 + t) * D + d];
        out_q[(size_t)(t0 + t) * D + d] = xv + (q - xv);
    }
}

// ---------------------------------------------------------------------------
// Finalize: loss = m + 0.25*m, m = mean(best_dist) over N*D elements
// ---------------------------------------------------------------------------
__global__ void finalize_kernel(float* __restrict__ out_loss, double inv_count) {
    __shared__ u64 sh[256];
    u64 s = 0;
    for (int i = threadIdx.x; i < NBLOCKS; i += 256) s += g_block_loss[i];
    sh[threadIdx.x] = s;
    __syncthreads();
    for (int st = 128; st > 0; st >>= 1) {
        if (threadIdx.x < st) sh[threadIdx.x] += sh[threadIdx.x + st];
        __syncthreads();
    }
    if (threadIdx.x == 0) {
        double tot = (double)sh[0] * (1.0 / 1073741824.0);
        float  m   = (float)(tot * inv_count);
        out_loss[0] = m + 0.25f * m;
    }
}

extern "C" void kernel_launch(void* const* d_in, const int* in_sizes, int n_in,
                              void* d_out, int out_size) {
    const float* x  = (const float*)d_in[0];
    const float* cb = (const float*)d_in[1];
    float* out = (float*)d_out;

    const int n = in_sizes[0] / D;            // 262144 tokens
    float* out_q    = out;
    float* out_loss = out + (size_t)n * D;
    float* out_idx  = out_loss + 1;

    cudaFuncSetAttribute(vq_kernel, cudaFuncAttributeMaxDynamicSharedMemorySize,
                         SMEM_TOTAL);

    prep_kernel<<<NCODES / 128, 128>>>(cb);
    vq_kernel<<<n / BT, 256, SMEM_TOTAL>>>(x, cb, out_q, out_idx);
    finalize_kernel<<<1, 256>>>(out_loss, 1.0 / ((double)n * D));
}